// round 9
// baseline (speedup 1.0000x reference)
#include <cuda_runtime.h>
#include <cuda_bf16.h>
#include <cstdint>
#include <cstddef>

typedef unsigned long long ull;

#define TSTEPS 1024
#define GDIM   1024
#define HSEQ   ((size_t)TSTEPS * 256 * 256)

__device__ float g_xpb[(size_t)TSTEPS * 256 * GDIM];   // x@W_ih + bias

__device__ __forceinline__ float f2tf(float x) {
    uint32_t r; asm("cvt.rna.tf32.f32 %0, %1;" : "=r"(r) : "f"(x));
    return __uint_as_float(r);
}
__device__ __forceinline__ uint32_t sptr(const void* p) {
    return (uint32_t)__cvta_generic_to_shared(p);
}
__device__ __forceinline__ void ldsm4(uint32_t a[4], uint32_t addr) {
    asm volatile("ldmatrix.sync.aligned.m8n8.x4.shared.b16 {%0,%1,%2,%3}, [%4];"
        : "=r"(a[0]), "=r"(a[1]), "=r"(a[2]), "=r"(a[3]) : "r"(addr));
}
__device__ __forceinline__ void mma8(float c[4], const uint32_t a[4], uint32_t b0, uint32_t b1) {
    asm volatile("mma.sync.aligned.m16n8k8.row.col.f32.tf32.tf32.f32 "
        "{%0,%1,%2,%3}, {%4,%5,%6,%7}, {%8,%9}, {%0,%1,%2,%3};"
        : "+f"(c[0]), "+f"(c[1]), "+f"(c[2]), "+f"(c[3])
        : "r"(a[0]), "r"(a[1]), "r"(a[2]), "r"(a[3]), "r"(b0), "r"(b1));
}
__device__ __forceinline__ float sigf(float x) { return 1.f / (1.f + __expf(-x)); }
__device__ __forceinline__ uint32_t mapa_rank(uint32_t addr, uint32_t rank) {
    uint32_t r;
    asm("mapa.shared::cluster.u32 %0, %1, %2;" : "=r"(r) : "r"(addr), "r"(rank));
    return r;
}
__device__ __forceinline__ void mbar_init(uint32_t a, uint32_t cnt) {
    asm volatile("mbarrier.init.shared.b64 [%0], %1;" :: "r"(a), "r"(cnt) : "memory");
}
__device__ __forceinline__ void mbar_expect(uint32_t a, uint32_t bytes) {
    asm volatile("mbarrier.arrive.expect_tx.shared.b64 _, [%0], %1;" :: "r"(a), "r"(bytes) : "memory");
}
__device__ __forceinline__ void mbar_wait(uint32_t a, uint32_t parity) {
    asm volatile(
        "{\n\t.reg .pred P;\n\t"
        "WL_%=:\n\t"
        "mbarrier.try_wait.parity.acquire.cta.shared::cta.b64 P, [%0], %1, 0x989680;\n\t"
        "@P bra.uni WD_%=;\n\t"
        "bra.uni WL_%=;\n\t"
        "WD_%=:\n\t}"
        :: "r"(a), "r"(parity) : "memory");
}
__device__ __forceinline__ void bulk_s2s(uint32_t dst, uint32_t src, uint32_t bytes, uint32_t mbar) {
    asm volatile("cp.async.bulk.shared::cluster.shared::cta.mbarrier::complete_tx::bytes "
                 "[%0], [%1], %2, [%3];"
        :: "r"(dst), "r"(src), "r"(bytes), "r"(mbar) : "memory");
}
__device__ __forceinline__ void bar_sync(int id, int cnt) {
    asm volatile("bar.sync %0, %1;" :: "r"(id), "r"(cnt) : "memory");
}
__device__ __forceinline__ void bar_arrive(int id, int cnt) {
    asm volatile("bar.arrive %0, %1;" :: "r"(id), "r"(cnt) : "memory");
}
__device__ __forceinline__ void cpa16(uint32_t dst, const float* src) {
    asm volatile("cp.async.cg.shared.global [%0], [%1], 16;" :: "r"(dst), "l"(src) : "memory");
}

// ============================================================================
// Projection (R7 version, measured ~0.92ms — keep)
// ============================================================================
#define PASTR 68
#define PBSTR 136
#define PROJ_SMEM ((128 * PASTR + 64 * PBSTR) * 4)

__global__ void __launch_bounds__(256) proj_kernel(const float* __restrict__ X,
                                                   const float* __restrict__ W,
                                                   const float* __restrict__ bias) {
    extern __shared__ float sm[];
    float* As = sm;
    float* Bs = sm + 128 * PASTR;
    const int tid = threadIdx.x;
    const int nb = blockIdx.x * 128, mb = blockIdx.y * 128;
    const int w = tid >> 5, lane = tid & 31;
    const int g = lane >> 2, t4 = lane & 3;
    const int mw = w & 1, nw = w >> 1;

    float acc[4][4][4] = {};
    const uint32_t abase = sptr(As + (mw * 64 + (lane & 15)) * PASTR + (lane >> 4) * 4);

    for (int kc = 0; kc < 4; kc++) {
        if (kc) __syncthreads();
        #pragma unroll
        for (int i = 0; i < 8; i++) {
            int idx = tid + 256 * i, r = idx >> 4, c4 = idx & 15;
            float4 v = *(const float4*)(X + (size_t)(mb + r) * 256 + kc * 64 + c4 * 4);
            v.x = f2tf(v.x); v.y = f2tf(v.y); v.z = f2tf(v.z); v.w = f2tf(v.w);
            *(float4*)(As + r * PASTR + c4 * 4) = v;
        }
        #pragma unroll
        for (int i = 0; i < 8; i++) {
            int idx = tid + 256 * i, r = idx >> 5, c4 = idx & 31;
            float4 v = *(const float4*)(W + (size_t)(kc * 64 + r) * GDIM + nb + c4 * 4);
            v.x = f2tf(v.x); v.y = f2tf(v.y); v.z = f2tf(v.z); v.w = f2tf(v.w);
            *(float4*)(Bs + r * PBSTR + c4 * 4) = v;
        }
        __syncthreads();
        #pragma unroll
        for (int kt = 0; kt < 8; kt++) {
            uint32_t af[4][4];
            #pragma unroll
            for (int mt = 0; mt < 4; mt++)
                ldsm4(af[mt], abase + (uint32_t)(mt * 16 * PASTR * 4) + kt * 32);
            #pragma unroll
            for (int nt = 0; nt < 4; nt++) {
                int col = nw * 32 + nt * 8 + g;
                uint32_t b0 = __float_as_uint(Bs[(kt * 8 + t4) * PBSTR + col]);
                uint32_t b1 = __float_as_uint(Bs[(kt * 8 + t4 + 4) * PBSTR + col]);
                #pragma unroll
                for (int mt = 0; mt < 4; mt++) mma8(acc[mt][nt], af[mt], b0, b1);
            }
        }
    }
    #pragma unroll
    for (int mt = 0; mt < 4; mt++) {
        size_t r0 = (size_t)(mb + mw * 64 + mt * 16 + g);
        #pragma unroll
        for (int nt = 0; nt < 4; nt++) {
            int col = nb + nw * 32 + nt * 8 + 2 * t4;
            float b0 = __ldg(bias + col), b1 = __ldg(bias + col + 1);
            *(float2*)(g_xpb + r0 * GDIM + col) =
                make_float2(acc[mt][nt][0] + b0, acc[mt][nt][1] + b1);
            *(float2*)(g_xpb + (r0 + 8) * GDIM + col) =
                make_float2(acc[mt][nt][2] + b0, acc[mt][nt][3] + b1);
        }
    }
}

// ============================================================================
// Recurrence: 8 clusters x 8 CTAs x 320 threads. Warps 0-7 = MMA (W_hh frags
// in regs), warps 8-9 = EPI (pointwise, c-state, stage, bulk push, out, xp via
// cp.async double-buffer). Named-barrier handoffs; R6 bulk DSMEM exchange.
// SMEM floats: As[gi][b] 4x4096 | gs[gi] 2x2112 | stage[gi][p] 4x512 |
//              xbuf[buf][gi] 4x2048 | 4 mbarriers
// ============================================================================
#define GSTR 132
#define AS_F(gi,b)  (((gi)*2+(b))*4096)
#define GS_F(gi)    (16384 + (gi)*2112)
#define ST_F(gi,p)  (20608 + ((gi)*2+(p))*512)
#define XB_F(bu,gi) (22656 + ((bu)*2+(gi))*2048)
#define MB_BYTE     123392
#define LSMEM_BYTES 123424

__global__ void __launch_bounds__(320, 1) __cluster_dims__(8, 1, 1)
lstm_kernel(const float* __restrict__ Whh, float* __restrict__ out, int tail) {
    extern __shared__ float smem[];
    const uint32_t smem0 = sptr(smem);
    const int tid = threadIdx.x;
    const int cid = blockIdx.x >> 3;           // 0..7, rows [32cid, 32cid+32)
    uint32_t r; asm("mov.u32 %0, %%cluster_ctarank;" : "=r"(r));

    if (tid == 0) {
        #pragma unroll
        for (int i = 0; i < 4; i++) mbar_init(smem0 + MB_BYTE + i * 8, 1);
        #pragma unroll
        for (int i = 0; i < 4; i++) mbar_expect(smem0 + MB_BYTE + i * 8, 16384);
    }
    __syncthreads();
    asm volatile("barrier.cluster.arrive.aligned;" ::: "memory");
    asm volatile("barrier.cluster.wait.aligned;" ::: "memory");

    if (tid < 256) {
        // ===================== MMA role (warps 0-7) =====================
        const int w = tid >> 5, lane = tid & 31;
        const int g = lane >> 2, t4 = lane & 3;
        uint32_t bf[32][2][2];
        #pragma unroll
        for (int kt = 0; kt < 32; kt++)
            #pragma unroll
            for (int nt = 0; nt < 2; nt++) {
                int l = w * 16 + nt * 8 + g;
                int gcol = (l >> 5) * 256 + (int)r * 32 + (l & 31);
                bf[kt][nt][0] = __float_as_uint(f2tf(Whh[(size_t)(kt * 8 + t4) * GDIM + gcol]));
                bf[kt][nt][1] = __float_as_uint(f2tf(Whh[(size_t)(kt * 8 + t4 + 4) * GDIM + gcol]));
            }
        const int laneRow = lane & 15, cb = lane >> 4, rx = laneRow & 7;
        const uint32_t rowbase = (uint32_t)laneRow * 128;
        int ph[2][2] = {{0, 0}, {0, 0}};

        for (int t = 0; t < TSTEPS; t++) {
            const int b = t & 1;
            #pragma unroll 1
            for (int gi = 0; gi < 2; gi++) {
                float acc[2][4] = {}, acc2[2][4] = {};
                if (t) {
                    uint32_t mb = smem0 + MB_BYTE + (gi * 2 + b) * 8;
                    mbar_wait(mb, (uint32_t)ph[gi][b]);
                    ph[gi][b] ^= 1;
                    if (tid == 0) mbar_expect(mb, 16384);
                    uint32_t ab = smem0 + AS_F(gi, b) * 4 + rowbase;
                    #pragma unroll
                    for (int kt = 0; kt < 16; kt++) {
                        uint32_t a[4];
                        uint32_t c = (uint32_t)(((((kt & 3) << 1) | cb) ^ rx) << 4);
                        ldsm4(a, ab + ((kt >> 2) << 11) + c);
                        mma8(acc[0], a, bf[kt][0][0], bf[kt][0][1]);
                        mma8(acc[1], a, bf[kt][1][0], bf[kt][1][1]);
                    }
                    #pragma unroll
                    for (int kt = 16; kt < 32; kt++) {
                        uint32_t a[4];
                        uint32_t c = (uint32_t)(((((kt & 3) << 1) | cb) ^ rx) << 4);
                        ldsm4(a, ab + ((kt >> 2) << 11) + c);
                        mma8(acc2[0], a, bf[kt][0][0], bf[kt][0][1]);
                        mma8(acc2[1], a, bf[kt][1][0], bf[kt][1][1]);
                    }
                    bar_sync(3 + gi, 320);   // epi released gs[gi] from t-1
                }
                float* gsp = smem + GS_F(gi);
                #pragma unroll
                for (int nt = 0; nt < 2; nt++) {
                    int lc = w * 16 + nt * 8 + 2 * t4;
                    *(float2*)&gsp[g * GSTR + lc] =
                        make_float2(acc[nt][0] + acc2[nt][0], acc[nt][1] + acc2[nt][1]);
                    *(float2*)&gsp[(g + 8) * GSTR + lc] =
                        make_float2(acc[nt][2] + acc2[nt][2], acc[nt][3] + acc2[nt][3]);
                }
                bar_arrive(1 + gi, 320);     // gates ready for epi
            }
        }
        bar_sync(3, 320);                    // drain epi's final releases
        bar_sync(4, 320);
    } else {
        // ===================== EPI role (warps 8-9) =====================
        const int e = tid - 256;             // 0..63
        const int row = e >> 2;              // 0..15 within group
        const int c8 = (e & 3) * 8;          // 0,8,16,24
        const int ch0 = (2 * (e & 3)) ^ (row & 7);
        const int ch1 = (2 * (e & 3) + 1) ^ (row & 7);
        float cst[2][8] = {};

        // prime xp for t=0 into xbuf[0]
        #pragma unroll
        for (int gi = 0; gi < 2; gi++)
            #pragma unroll
            for (int ga = 0; ga < 4; ga++) {
                const float* src = g_xpb + (size_t)(cid * 32 + gi * 16 + row) * GDIM
                                 + ga * 256 + (int)r * 32 + c8;
                uint32_t dst = smem0 + (uint32_t)(XB_F(0, gi) + row * 128 + ga * 32 + c8) * 4;
                cpa16(dst, src);
                cpa16(dst + 16, src + 4);
            }
        asm volatile("cp.async.commit_group;" ::: "memory");

        for (int t = 0; t < TSTEPS; t++) {
            const int b = t & 1;
            // prefetch xp for t+1 into xbuf[b^1]
            if (t + 1 < TSTEPS) {
                #pragma unroll
                for (int gi = 0; gi < 2; gi++)
                    #pragma unroll
                    for (int ga = 0; ga < 4; ga++) {
                        const float* src = g_xpb + (size_t)(t + 1) * (256 * GDIM)
                                         + (size_t)(cid * 32 + gi * 16 + row) * GDIM
                                         + ga * 256 + (int)r * 32 + c8;
                        uint32_t dst = smem0
                            + (uint32_t)(XB_F(b ^ 1, gi) + row * 128 + ga * 32 + c8) * 4;
                        cpa16(dst, src);
                        cpa16(dst + 16, src + 4);
                    }
            }
            asm volatile("cp.async.commit_group;" ::: "memory");
            asm volatile("cp.async.wait_group 1;" ::: "memory");

            #pragma unroll 1
            for (int gi = 0; gi < 2; gi++) {
                bar_sync(1 + gi, 320);       // wait gates from mma
                float gg[4][8];
                float* gsp = smem + GS_F(gi);
                #pragma unroll
                for (int ga = 0; ga < 4; ga++) {
                    float4 a = *(float4*)&gsp[row * GSTR + ga * 32 + c8];
                    float4 b2 = *(float4*)&gsp[row * GSTR + ga * 32 + c8 + 4];
                    gg[ga][0] = a.x; gg[ga][1] = a.y; gg[ga][2] = a.z; gg[ga][3] = a.w;
                    gg[ga][4] = b2.x; gg[ga][5] = b2.y; gg[ga][6] = b2.z; gg[ga][7] = b2.w;
                }
                bar_arrive(3 + gi, 320);     // release gs[gi]
                // xp from SMEM double buffer
                float* xb = smem + XB_F(b, gi) + row * 128 + c8;
                float xx[4][8];
                #pragma unroll
                for (int ga = 0; ga < 4; ga++) {
                    float4 a = *(float4*)(xb + ga * 32);
                    float4 b2 = *(float4*)(xb + ga * 32 + 4);
                    xx[ga][0] = a.x; xx[ga][1] = a.y; xx[ga][2] = a.z; xx[ga][3] = a.w;
                    xx[ga][4] = b2.x; xx[ga][5] = b2.y; xx[ga][6] = b2.z; xx[ga][7] = b2.w;
                }
                float h[8];
                #pragma unroll
                for (int j = 0; j < 8; j++) {
                    float iv = sigf(gg[0][j] + xx[0][j]);
                    float fv = sigf(gg[1][j] + xx[1][j]);
                    float Gv = tanhf(gg[2][j] + xx[2][j]);
                    float ov = sigf(gg[3][j] + xx[3][j]);
                    cst[gi][j] = fv * cst[gi][j] + iv * Gv;
                    h[j] = ov * tanhf(cst[gi][j]);
                }
                // stage swizzled tf32 block
                float* st = smem + ST_F(gi, b);
                *(float4*)&st[row * 32 + ch0 * 4] =
                    make_float4(f2tf(h[0]), f2tf(h[1]), f2tf(h[2]), f2tf(h[3]));
                *(float4*)&st[row * 32 + ch1 * 4] =
                    make_float4(f2tf(h[4]), f2tf(h[5]), f2tf(h[6]), f2tf(h[7]));
                bar_sync(5, 64);             // epi-internal: stage complete
                if (e == 0 && t < TSTEPS - 1) {
                    asm volatile("fence.proxy.async.shared::cta;" ::: "memory");
                    uint32_t src = smem0 + (uint32_t)ST_F(gi, b) * 4;
                    uint32_t dstl = smem0 + (uint32_t)AS_F(gi, b ^ 1) * 4 + r * 2048;
                    uint32_t mbl = smem0 + MB_BYTE + (gi * 2 + (b ^ 1)) * 8;
                    #pragma unroll
                    for (uint32_t dr = 0; dr < 8; dr++)
                        bulk_s2s(mapa_rank(dstl, dr), src, 2048u, mapa_rank(mbl, dr));
                }
                // stream h out (off critical path)
                size_t off = (size_t)(cid * 32 + gi * 16 + row) * 256 + (int)r * 32 + c8;
                *(float4*)(out + (size_t)t * 65536 + off) =
                    make_float4(h[0], h[1], h[2], h[3]);
                *(float4*)(out + (size_t)t * 65536 + off + 4) =
                    make_float4(h[4], h[5], h[6], h[7]);
                if (tail && t == TSTEPS - 1) {
                    *(float4*)(out + HSEQ + off) = make_float4(h[0], h[1], h[2], h[3]);
                    *(float4*)(out + HSEQ + off + 4) = make_float4(h[4], h[5], h[6], h[7]);
                    *(float4*)(out + HSEQ + 65536 + off) =
                        make_float4(cst[gi][0], cst[gi][1], cst[gi][2], cst[gi][3]);
                    *(float4*)(out + HSEQ + 65536 + off + 4) =
                        make_float4(cst[gi][4], cst[gi][5], cst[gi][6], cst[gi][7]);
                }
            }
        }
        if (e == 0) {
            asm volatile("cp.async.bulk.commit_group;" ::: "memory");
            asm volatile("cp.async.bulk.wait_group.read 0;" ::: "memory");
        }
    }
    __syncthreads();
    asm volatile("barrier.cluster.arrive.aligned;" ::: "memory");
    asm volatile("barrier.cluster.wait.aligned;" ::: "memory");
}

extern "C" void kernel_launch(void* const* d_in, const int* in_sizes, int n_in,
                              void* d_out, int out_size) {
    const float* x    = (const float*)d_in[0];
    const float* wih  = (const float*)d_in[1];
    const float* whh  = (const float*)d_in[2];
    const float* bias = (const float*)d_in[3];
    float* out = (float*)d_out;
    (void)in_sizes; (void)n_in;
    cudaFuncSetAttribute(proj_kernel, cudaFuncAttributeMaxDynamicSharedMemorySize, PROJ_SMEM);
    cudaFuncSetAttribute(lstm_kernel, cudaFuncAttributeMaxDynamicSharedMemorySize, LSMEM_BYTES);
    proj_kernel<<<dim3(8, 2048), 256, PROJ_SMEM>>>(x, wih, bias);
    int tail = ((size_t)out_size >= HSEQ + 2 * 65536) ? 1 : 0;
    lstm_kernel<<<64, 320, LSMEM_BYTES>>>(whh, out, tail);
}

// round 10
// speedup vs baseline: 1.7011x; 1.7011x over previous
#include <cuda_runtime.h>
#include <cuda_fp16.h>
#include <cstdint>
#include <cstddef>

typedef unsigned long long ull;

#define TSTEPS 1024
#define GDIM   1024
#define HSEQ   ((size_t)TSTEPS * 256 * 256)

__device__ float g_xpb[(size_t)TSTEPS * 256 * GDIM];   // x@W_ih + bias

__device__ __forceinline__ float f2tf(float x) {
    uint32_t r; asm("cvt.rna.tf32.f32 %0, %1;" : "=r"(r) : "f"(x));
    return __uint_as_float(r);
}
__device__ __forceinline__ uint32_t packh2(float lo, float hi) {
    uint32_t u;
    asm("cvt.rn.f16x2.f32 %0, %1, %2;" : "=r"(u) : "f"(hi), "f"(lo));
    return u;
}
__device__ __forceinline__ uint32_t sptr(const void* p) {
    return (uint32_t)__cvta_generic_to_shared(p);
}
__device__ __forceinline__ void ldsm4(uint32_t a[4], uint32_t addr) {
    asm volatile("ldmatrix.sync.aligned.m8n8.x4.shared.b16 {%0,%1,%2,%3}, [%4];"
        : "=r"(a[0]), "=r"(a[1]), "=r"(a[2]), "=r"(a[3]) : "r"(addr));
}
__device__ __forceinline__ void mma_tf32(float c[4], const uint32_t a[4], uint32_t b0, uint32_t b1) {
    asm volatile("mma.sync.aligned.m16n8k8.row.col.f32.tf32.tf32.f32 "
        "{%0,%1,%2,%3}, {%4,%5,%6,%7}, {%8,%9}, {%0,%1,%2,%3};"
        : "+f"(c[0]), "+f"(c[1]), "+f"(c[2]), "+f"(c[3])
        : "r"(a[0]), "r"(a[1]), "r"(a[2]), "r"(a[3]), "r"(b0), "r"(b1));
}
__device__ __forceinline__ void mma_f16(float c[4], const uint32_t a[4], uint32_t b0, uint32_t b1) {
    asm volatile("mma.sync.aligned.m16n8k16.row.col.f32.f16.f16.f32 "
        "{%0,%1,%2,%3}, {%4,%5,%6,%7}, {%8,%9}, {%0,%1,%2,%3};"
        : "+f"(c[0]), "+f"(c[1]), "+f"(c[2]), "+f"(c[3])
        : "r"(a[0]), "r"(a[1]), "r"(a[2]), "r"(a[3]), "r"(b0), "r"(b1));
}
__device__ __forceinline__ float sigf(float x) { return 1.f / (1.f + __expf(-x)); }
__device__ __forceinline__ uint32_t mapa_rank(uint32_t addr, uint32_t rank) {
    uint32_t r;
    asm("mapa.shared::cluster.u32 %0, %1, %2;" : "=r"(r) : "r"(addr), "r"(rank));
    return r;
}
__device__ __forceinline__ void mbar_init(uint32_t a, uint32_t cnt) {
    asm volatile("mbarrier.init.shared.b64 [%0], %1;" :: "r"(a), "r"(cnt) : "memory");
}
__device__ __forceinline__ void mbar_expect(uint32_t a, uint32_t bytes) {
    asm volatile("mbarrier.arrive.expect_tx.shared.b64 _, [%0], %1;" :: "r"(a), "r"(bytes) : "memory");
}
__device__ __forceinline__ void mbar_wait(uint32_t a, uint32_t parity) {
    asm volatile(
        "{\n\t.reg .pred P;\n\t"
        "WL_%=:\n\t"
        "mbarrier.try_wait.parity.acquire.cta.shared::cta.b64 P, [%0], %1, 0x989680;\n\t"
        "@P bra.uni WD_%=;\n\t"
        "bra.uni WL_%=;\n\t"
        "WD_%=:\n\t}"
        :: "r"(a), "r"(parity) : "memory");
}
__device__ __forceinline__ void bulk_s2s(uint32_t dst, uint32_t src, uint32_t bytes, uint32_t mbar) {
    asm volatile("cp.async.bulk.shared::cluster.shared::cta.mbarrier::complete_tx::bytes "
                 "[%0], [%1], %2, [%3];"
        :: "r"(dst), "r"(src), "r"(bytes), "r"(mbar) : "memory");
}

// ============================================================================
// Projection (R7 version, measured ~0.92ms — keep)
// ============================================================================
#define PASTR 68
#define PBSTR 136
#define PROJ_SMEM ((128 * PASTR + 64 * PBSTR) * 4)

__global__ void __launch_bounds__(256) proj_kernel(const float* __restrict__ X,
                                                   const float* __restrict__ W,
                                                   const float* __restrict__ bias) {
    extern __shared__ float sm[];
    float* As = sm;
    float* Bs = sm + 128 * PASTR;
    const int tid = threadIdx.x;
    const int nb = blockIdx.x * 128, mb = blockIdx.y * 128;
    const int w = tid >> 5, lane = tid & 31;
    const int g = lane >> 2, t4 = lane & 3;
    const int mw = w & 1, nw = w >> 1;

    float acc[4][4][4] = {};
    const uint32_t abase = sptr(As + (mw * 64 + (lane & 15)) * PASTR + (lane >> 4) * 4);

    for (int kc = 0; kc < 4; kc++) {
        if (kc) __syncthreads();
        #pragma unroll
        for (int i = 0; i < 8; i++) {
            int idx = tid + 256 * i, r = idx >> 4, c4 = idx & 15;
            float4 v = *(const float4*)(X + (size_t)(mb + r) * 256 + kc * 64 + c4 * 4);
            v.x = f2tf(v.x); v.y = f2tf(v.y); v.z = f2tf(v.z); v.w = f2tf(v.w);
            *(float4*)(As + r * PASTR + c4 * 4) = v;
        }
        #pragma unroll
        for (int i = 0; i < 8; i++) {
            int idx = tid + 256 * i, r = idx >> 5, c4 = idx & 31;
            float4 v = *(const float4*)(W + (size_t)(kc * 64 + r) * GDIM + nb + c4 * 4);
            v.x = f2tf(v.x); v.y = f2tf(v.y); v.z = f2tf(v.z); v.w = f2tf(v.w);
            *(float4*)(Bs + r * PBSTR + c4 * 4) = v;
        }
        __syncthreads();
        #pragma unroll
        for (int kt = 0; kt < 8; kt++) {
            uint32_t af[4][4];
            #pragma unroll
            for (int mt = 0; mt < 4; mt++)
                ldsm4(af[mt], abase + (uint32_t)(mt * 16 * PASTR * 4) + kt * 32);
            #pragma unroll
            for (int nt = 0; nt < 4; nt++) {
                int col = nw * 32 + nt * 8 + g;
                uint32_t b0 = __float_as_uint(Bs[(kt * 8 + t4) * PBSTR + col]);
                uint32_t b1 = __float_as_uint(Bs[(kt * 8 + t4 + 4) * PBSTR + col]);
                #pragma unroll
                for (int mt = 0; mt < 4; mt++) mma_tf32(acc[mt][nt], af[mt], b0, b1);
            }
        }
    }
    #pragma unroll
    for (int mt = 0; mt < 4; mt++) {
        size_t r0 = (size_t)(mb + mw * 64 + mt * 16 + g);
        #pragma unroll
        for (int nt = 0; nt < 4; nt++) {
            int col = nb + nw * 32 + nt * 8 + 2 * t4;
            float b0 = __ldg(bias + col), b1 = __ldg(bias + col + 1);
            *(float2*)(g_xpb + r0 * GDIM + col) =
                make_float2(acc[mt][nt][0] + b0, acc[mt][nt][1] + b1);
            *(float2*)(g_xpb + (r0 + 8) * GDIM + col) =
                make_float2(acc[mt][nt][2] + b0, acc[mt][nt][3] + b1);
        }
    }
}

// ============================================================================
// Recurrence: R6 topology (8 clusters x 8 CTAs x 256 thr, 2 groups/CTA),
// fp16 h + fp16 W_hh (mma.m16n8k16, fp32 accum). Exchange = 8 x 1KB bulk
// DSMEM pushes. Dest block layout per rank: addr = kt*512 + hi*256 + row*16.
// Byte offsets: As 4x8KB | gs 2x8448B | stage 2x1KB | 4 mbars
// ============================================================================
#define GSTR 132
#define AS_B(gi,b)  (((gi)*2+(b))*8192)
#define GS_B(gi)    (32768 + (gi)*8448)
#define ST_B(gi)    (49664 + (gi)*1024)
#define MB_B        51712
#define LSMEM_BYTES 51744

__global__ void __launch_bounds__(256, 1) __cluster_dims__(8, 1, 1)
lstm_kernel(const float* __restrict__ Whh, float* __restrict__ out, int tail) {
    extern __shared__ char smc[];
    float* smem = (float*)smc;
    const uint32_t smem0 = sptr(smc);
    const int tid = threadIdx.x;
    const int w = tid >> 5, lane = tid & 31;
    const int g = lane >> 2, t4 = lane & 3;
    const int cid = blockIdx.x >> 3;          // 0..7, rows [32cid, 32cid+32)
    uint32_t r; asm("mov.u32 %0, %%cluster_ctarank;" : "=r"(r));

    if (tid == 0) {
        #pragma unroll
        for (int i = 0; i < 4; i++) mbar_init(smem0 + MB_B + i * 8, 1);
        #pragma unroll
        for (int i = 0; i < 4; i++) mbar_expect(smem0 + MB_B + i * 8, 8192);
    }

    // W_hh slice as persistent fp16 mma B-fragments (64 regs)
    uint32_t bf[16][2][2];
    #pragma unroll
    for (int kt = 0; kt < 16; kt++)
        #pragma unroll
        for (int nt = 0; nt < 2; nt++) {
            int l = w * 16 + nt * 8 + g;
            int gcol = (l >> 5) * 256 + (int)r * 32 + (l & 31);
            bf[kt][nt][0] = packh2(Whh[(size_t)(kt * 16 + 2 * t4) * GDIM + gcol],
                                   Whh[(size_t)(kt * 16 + 2 * t4 + 1) * GDIM + gcol]);
            bf[kt][nt][1] = packh2(Whh[(size_t)(kt * 16 + 8 + 2 * t4) * GDIM + gcol],
                                   Whh[(size_t)(kt * 16 + 8 + 2 * t4 + 1) * GDIM + gcol]);
        }
    __syncthreads();
    asm volatile("barrier.cluster.arrive.aligned;" ::: "memory");
    asm volatile("barrier.cluster.wait.aligned;" ::: "memory");

    // ldsm lane offset within a buffer: kt*512 + (lane>>4)*256 + (lane&15)*16
    const uint32_t laneoff = (uint32_t)((lane >> 4) * 256 + (lane & 15) * 16);

    // pointwise / staging ownership: thread -> (row prow, cols pc,pc+1)
    const int prow = tid >> 4;          // 0..15
    const int pc = (tid & 15) * 2;      // 0..30
    const uint32_t stoff = (uint32_t)((pc >> 3) * 256 + prow * 16 + (pc & 7) * 2);
    float cst[2][2] = {};
    int ph[2][2] = {{0, 0}, {0, 0}};

    for (int t = 0; t < TSTEPS; t++) {
        const int b = t & 1, nbuf = b ^ 1;
        // prefetch xp for both groups (overlaps wait + mma)
        float2 xp[2][4];
        #pragma unroll
        for (int gi = 0; gi < 2; gi++) {
            const float* xr = g_xpb + (size_t)t * (256 * GDIM)
                            + (size_t)(cid * 32 + gi * 16 + prow) * GDIM + r * 32 + pc;
            xp[gi][0] = __ldcg((const float2*)xr);
            xp[gi][1] = __ldcg((const float2*)(xr + 256));
            xp[gi][2] = __ldcg((const float2*)(xr + 512));
            xp[gi][3] = __ldcg((const float2*)(xr + 768));
        }
        #pragma unroll
        for (int gi = 0; gi < 2; gi++) {
            float acc[2][4] = {}, acc2[2][4] = {};
            if (t) {
                uint32_t mb = smem0 + MB_B + (gi * 2 + b) * 8;
                mbar_wait(mb, (uint32_t)ph[gi][b]);
                ph[gi][b] ^= 1;
                if (tid == 0) mbar_expect(mb, 8192);
                uint32_t ab = smem0 + (uint32_t)AS_B(gi, b) + laneoff;
                #pragma unroll
                for (int kt = 0; kt < 8; kt++) {
                    uint32_t a[4];
                    ldsm4(a, ab + (uint32_t)(kt * 512));
                    mma_f16(acc[0], a, bf[kt][0][0], bf[kt][0][1]);
                    mma_f16(acc[1], a, bf[kt][1][0], bf[kt][1][1]);
                }
                #pragma unroll
                for (int kt = 8; kt < 16; kt++) {
                    uint32_t a[4];
                    ldsm4(a, ab + (uint32_t)(kt * 512));
                    mma_f16(acc2[0], a, bf[kt][0][0], bf[kt][0][1]);
                    mma_f16(acc2[1], a, bf[kt][1][0], bf[kt][1][1]);
                }
            }
            // scatter gates (fp32)
            float* gsp = (float*)(smc + GS_B(gi));
            #pragma unroll
            for (int nt = 0; nt < 2; nt++) {
                int lc = w * 16 + nt * 8 + 2 * t4;
                *(float2*)&gsp[g * GSTR + lc] =
                    make_float2(acc[nt][0] + acc2[nt][0], acc[nt][1] + acc2[nt][1]);
                *(float2*)&gsp[(g + 8) * GSTR + lc] =
                    make_float2(acc[nt][2] + acc2[nt][2], acc[nt][3] + acc2[nt][3]);
            }
            __syncthreads();
            // pointwise
            float2 vi = *(float2*)&gsp[prow * GSTR + pc];
            float2 vf = *(float2*)&gsp[prow * GSTR + 32 + pc];
            float2 vg = *(float2*)&gsp[prow * GSTR + 64 + pc];
            float2 vo = *(float2*)&gsp[prow * GSTR + 96 + pc];
            float i0 = sigf(vi.x + xp[gi][0].x), i1 = sigf(vi.y + xp[gi][0].y);
            float f0 = sigf(vf.x + xp[gi][1].x), f1 = sigf(vf.y + xp[gi][1].y);
            float G0 = tanhf(vg.x + xp[gi][2].x), G1 = tanhf(vg.y + xp[gi][2].y);
            float o0 = sigf(vo.x + xp[gi][3].x), o1 = sigf(vo.y + xp[gi][3].y);
            cst[gi][0] = f0 * cst[gi][0] + i0 * G0;
            cst[gi][1] = f1 * cst[gi][1] + i1 * G1;
            float h0 = o0 * tanhf(cst[gi][0]), h1 = o1 * tanhf(cst[gi][1]);
            // stage fp16 pair into chunk-major block
            *(uint32_t*)(smc + ST_B(gi) + stoff) = packh2(h0, h1);
            __syncthreads();
            // async push first (on the wire ASAP): 8 x 1KB with complete_tx
            if (tid == 0 && t < TSTEPS - 1) {
                asm volatile("fence.proxy.async.shared::cta;" ::: "memory");
                uint32_t src = smem0 + (uint32_t)ST_B(gi);
                uint32_t dstl = smem0 + (uint32_t)AS_B(gi, nbuf) + r * 1024;
                uint32_t mbl = smem0 + MB_B + (gi * 2 + nbuf) * 8;
                #pragma unroll
                for (uint32_t dr = 0; dr < 8; dr++)
                    bulk_s2s(mapa_rank(dstl, dr), src, 1024u, mapa_rank(mbl, dr));
            }
            // stream h out (off critical path)
            size_t off = (size_t)(cid * 32 + gi * 16 + prow) * 256 + r * 32 + pc;
            *(float2*)(out + (size_t)t * 65536 + off) = make_float2(h0, h1);
            if (tail && t == TSTEPS - 1) {
                *(float2*)(out + HSEQ + off) = make_float2(h0, h1);
                *(float2*)(out + HSEQ + 65536 + off) = make_float2(cst[gi][0], cst[gi][1]);
            }
        }
    }
    if (tid == 0) {
        asm volatile("cp.async.bulk.commit_group;" ::: "memory");
        asm volatile("cp.async.bulk.wait_group.read 0;" ::: "memory");
    }
    __syncthreads();
    asm volatile("barrier.cluster.arrive.aligned;" ::: "memory");
    asm volatile("barrier.cluster.wait.aligned;" ::: "memory");
}

extern "C" void kernel_launch(void* const* d_in, const int* in_sizes, int n_in,
                              void* d_out, int out_size) {
    const float* x    = (const float*)d_in[0];
    const float* wih  = (const float*)d_in[1];
    const float* whh  = (const float*)d_in[2];
    const float* bias = (const float*)d_in[3];
    float* out = (float*)d_out;
    (void)in_sizes; (void)n_in;
    cudaFuncSetAttribute(proj_kernel, cudaFuncAttributeMaxDynamicSharedMemorySize, PROJ_SMEM);
    cudaFuncSetAttribute(lstm_kernel, cudaFuncAttributeMaxDynamicSharedMemorySize, LSMEM_BYTES);
    proj_kernel<<<dim3(8, 2048), 256, PROJ_SMEM>>>(x, wih, bias);
    int tail = ((size_t)out_size >= HSEQ + 2 * 65536) ? 1 : 0;
    lstm_kernel<<<64, 256, LSMEM_BYTES>>>(whh, out, tail);
}